// round 1
// baseline (speedup 1.0000x reference)
#include <cuda_runtime.h>
#include <math.h>

#define B 4
#define H 8
#define T 8192
#define D 64
#define NC 128
#define W 64
#define BH (B*H)
#define NTOK (B*H*T)          /* 262144 */
#define NOUT (B*H*T*D)        /* 16777216 */
#define NBINS 4096
#define CANDCAP 512

// -------- device scratch (no allocations allowed) --------
__device__ float  g_dists[(size_t)B*H*2*NC*T];   // [bh][s][c][t]  268MB
__device__ float  g_mnorm2[H*NC];
__device__ int    g_qidx[B*H*NC*W];
__device__ int    g_kidx[B*H*NC*W];
__device__ float  g_cnt[NTOK];
__device__ double g_aux;

// ---------------------------------------------------------
__global__ void zero_kernel(float* out, int out_size) {
    int i = blockIdx.x * blockDim.x + threadIdx.x;
    if (i < out_size) out[i] = 0.0f;
    if (i < NTOK) g_cnt[i] = 0.0f;
    if (i == 0) g_aux = 0.0;
}

__global__ void mnorm_kernel(const float* __restrict__ means) {
    int i = blockIdx.x * blockDim.x + threadIdx.x;
    if (i < H * NC) {
        const float* m = means + (size_t)i * D;
        float s = 0.f;
        #pragma unroll
        for (int d = 0; d < D; d++) { float x = m[d]; s += x * x; }
        g_mnorm2[i] = s;
    }
}

// One block: 128 tokens, each thread = 1 token. Means tile in smem.
__global__ void dist_kernel(const float* __restrict__ q,
                            const float* __restrict__ k,
                            const float* __restrict__ means) {
    __shared__ float sm[NC * D];   // 32KB
    __shared__ float red[128];
    int h = blockIdx.y, b = blockIdx.z;
    int tid = threadIdx.x;
    const float* mh = means + (size_t)h * NC * D;
    for (int i = tid; i < NC * D; i += 128) sm[i] = mh[i];
    __syncthreads();

    int l = blockIdx.x * 128 + tid;            // [0, 2T)
    int s = (l >= T) ? 1 : 0;
    int tloc = s ? (l - T) : l;
    const float* src = s ? k : q;
    const float* xr = src + ((size_t)(b * H + h) * T + tloc) * D;

    float4 x4[16];
    float n2 = 0.f;
    #pragma unroll
    for (int i = 0; i < 16; i++) {
        float4 v = ((const float4*)xr)[i];
        x4[i] = v;
        n2 += v.x * v.x + v.y * v.y + v.z * v.z + v.w * v.w;
    }
    float nrm = sqrtf(n2);
    float inv = 1.0f / fmaxf(nrm, 1e-12f);
    #pragma unroll
    for (int i = 0; i < 16; i++) {
        x4[i].x *= inv; x4[i].y *= inv; x4[i].z *= inv; x4[i].w *= inv;
    }
    float xn2 = n2 * inv * inv;

    size_t base = (((size_t)(b * H + h) * 2 + s) * NC) * T + tloc;
    const float4* sm4 = (const float4*)sm;
    float dmax = -1e30f; int cmax = 0;
    for (int c = 0; c < NC; c++) {
        float acc = 0.f;
        #pragma unroll
        for (int i = 0; i < 16; i++) {
            float4 m = sm4[c * 16 + i];
            acc += x4[i].x * m.x + x4[i].y * m.y + x4[i].z * m.z + x4[i].w * m.w;
        }
        g_dists[base + (size_t)c * T] = acc;
        if (acc > dmax) { dmax = acc; cmax = c; }   // first-max on ties (jnp.argmax)
    }
    float contrib = xn2 - 2.f * dmax + g_mnorm2[h * NC + cmax];
    red[tid] = contrib; __syncthreads();
    for (int o = 64; o > 0; o >>= 1) {
        if (tid < o) red[tid] += red[tid + o];
        __syncthreads();
    }
    if (tid == 0) atomicAdd(&g_aux, (double)red[0]);
}

// One block per (bh, s, c): exact top-64 via value-range histogram + exact
// tie-break in the threshold bin. Output SET matches jax.lax.top_k exactly.
extern __shared__ float tk_dyn[];   // sv[T] then hist[NBINS]
__global__ void topk_kernel() {
    float* sv = tk_dyn;                   // 8192 floats
    int* hist = (int*)(tk_dyn + T);       // 4096 ints
    __shared__ int   csum[256];
    __shared__ int   s_bstar, s_nAbove, s_nOut, s_nCand;
    __shared__ float candV[CANDCAP];
    __shared__ int   candI[CANDCAP];

    int bid = blockIdx.x;
    int c = bid % NC;
    int s = (bid / NC) & 1;
    int bh = bid / (2 * NC);
    int h = bh % H;
    int tid = threadIdx.x;

    const float* dp = g_dists + (((size_t)bh * 2 + s) * NC + c) * T;
    for (int i = tid; i < T; i += 256) sv[i] = dp[i];
    for (int i = tid; i < NBINS; i += 256) hist[i] = 0;
    if (tid == 0) { s_nOut = 0; s_nCand = 0; }
    __syncthreads();

    float mn = sqrtf(g_mnorm2[h * NC + c]);
    float lo = -mn;
    float scaleb = (float)NBINS / (2.0f * mn);

    for (int i = tid; i < T; i += 256) {
        int bin = (int)((sv[i] - lo) * scaleb);
        bin = min(max(bin, 0), NBINS - 1);
        atomicAdd(&hist[bin], 1);
    }
    __syncthreads();

    // per-thread chunk of 16 bins; inclusive suffix scan over 256 chunks
    int orig = 0;
    #pragma unroll
    for (int bb = 0; bb < 16; bb++) orig += hist[tid * 16 + bb];
    csum[tid] = orig; __syncthreads();
    for (int st = 1; st < 256; st <<= 1) {
        int add = (tid + st < 256) ? csum[tid + st] : 0;
        __syncthreads();
        csum[tid] += add;
        __syncthreads();
    }
    int E = csum[tid] - orig;   // count strictly above this chunk
    if (E < W && E + orig >= W) {
        int cum = E;
        for (int bb = 15; bb >= 0; bb--) {
            int hc = hist[tid * 16 + bb];
            if (cum + hc >= W) { s_bstar = tid * 16 + bb; s_nAbove = cum; break; }
            cum += hc;
        }
    }
    __syncthreads();
    int bstar = s_bstar;

    int* outPtr = (s == 0 ? g_qidx : g_kidx) + ((size_t)bh * NC + c) * W;
    for (int i = tid; i < T; i += 256) {
        int bin = (int)((sv[i] - lo) * scaleb);
        bin = min(max(bin, 0), NBINS - 1);
        if (bin > bstar) {
            int p = atomicAdd(&s_nOut, 1);
            outPtr[p] = i;
        } else if (bin == bstar) {
            int p = atomicAdd(&s_nCand, 1);
            if (p < CANDCAP) { candV[p] = sv[i]; candI[p] = i; }
        }
    }
    __syncthreads();

    if (tid == 0) {
        int nOut = s_nOut;                  // == s_nAbove
        int need = W - nOut;
        int ncand = min(s_nCand, CANDCAP);
        for (int r = 0; r < need; r++) {
            float bv = -1e30f; int bi = 0x7fffffff; int bp = -1;
            for (int m = 0; m < ncand; m++) {
                if (candI[m] >= 0) {
                    float vv = candV[m];
                    if (vv > bv || (vv == bv && candI[m] < bi)) { bv = vv; bi = candI[m]; bp = m; }
                }
            }
            outPtr[nOut + r] = bi;
            candI[bp] = -1;
        }
    }
}

// One block per (bh, c) window: 64 q x 65 kv, d=64; scalar fp32 + atomic scatter.
extern __shared__ float at_dyn[];
__global__ void attn_kernel(const float* __restrict__ q,
                            const float* __restrict__ k,
                            const float* __restrict__ v,
                            const float* __restrict__ mem_key,
                            const float* __restrict__ mem_value,
                            float* __restrict__ out) {
    float* qs = at_dyn;            // 64*64
    float* ks = qs + 64 * 64;      // 65*64
    float* vs = ks + 65 * 64;      // 65*64
    float* sc = vs + 65 * 64;      // 64*65
    int* qi = (int*)(sc + 64 * 65);
    int* ki = qi + 64;

    int bid = blockIdx.x;
    int c = bid % NC;
    int bh = bid / NC;
    int h = bh % H;
    int tid = threadIdx.x;

    if (tid < 64)       qi[tid]       = g_qidx[((size_t)bh * NC + c) * W + tid];
    else if (tid < 128) ki[tid - 64]  = g_kidx[((size_t)bh * NC + c) * W + tid - 64];
    __syncthreads();

    for (int idx = tid; idx < 64 * 64; idx += 256) {
        int r = idx >> 6, col = idx & 63;
        qs[idx] = q[((size_t)bh * T + qi[r]) * D + col];
    }
    for (int idx = tid; idx < 65 * 64; idx += 256) {
        int r = idx >> 6, col = idx & 63;
        if (r == 0) {
            ks[idx] = mem_key[((size_t)h * NC + c) * D + col];
            vs[idx] = mem_value[((size_t)h * NC + c) * D + col];
        } else {
            ks[idx] = k[((size_t)bh * T + ki[r - 1]) * D + col];
            vs[idx] = v[((size_t)bh * T + ki[r - 1]) * D + col];
        }
    }
    __syncthreads();

    int qrow = tid >> 2, part = tid & 3;
    const float scale = 0.125f;   // d^-0.5

    const float4* qv = (const float4*)(qs + qrow * 64);
    for (int j = part; j < 65; j += 4) {
        const float4* kv = (const float4*)(ks + j * 64);
        float acc = 0.f;
        #pragma unroll
        for (int i = 0; i < 16; i++) {
            float4 a = qv[i], bb = kv[i];
            acc += a.x * bb.x + a.y * bb.y + a.z * bb.z + a.w * bb.w;
        }
        sc[qrow * 65 + j] = acc * scale;
    }
    __syncthreads();

    // softmax per row, 4 cooperating threads (same warp group-of-4)
    float mx = -1e30f;
    for (int j = part; j < 65; j += 4) mx = fmaxf(mx, sc[qrow * 65 + j]);
    mx = fmaxf(mx, __shfl_xor_sync(0xffffffffu, mx, 1));
    mx = fmaxf(mx, __shfl_xor_sync(0xffffffffu, mx, 2));
    float sum = 0.f;
    for (int j = part; j < 65; j += 4) {
        float e = __expf(sc[qrow * 65 + j] - mx);
        sc[qrow * 65 + j] = e;
        sum += e;
    }
    sum += __shfl_xor_sync(0xffffffffu, sum, 1);
    sum += __shfl_xor_sync(0xffffffffu, sum, 2);
    float rinv = 1.0f / sum;
    __syncwarp();

    float o[16];
    #pragma unroll
    for (int dd = 0; dd < 16; dd++) o[dd] = 0.f;
    int dbase = part * 16;
    for (int j = 0; j < 65; j++) {
        float w = sc[qrow * 65 + j] * rinv;
        const float* vr = vs + j * 64 + dbase;
        #pragma unroll
        for (int dd = 0; dd < 16; dd++) o[dd] += w * vr[dd];
    }

    int tok = qi[qrow];
    float* op = out + ((size_t)bh * T + tok) * D + dbase;
    #pragma unroll
    for (int dd = 0; dd < 16; dd++) atomicAdd(op + dd, o[dd]);
    if (part == 0) atomicAdd(&g_cnt[(size_t)bh * T + tok], 1.0f);
}

__global__ void finalize_kernel(float* out, int out_size) {
    int i = blockIdx.x * blockDim.x + threadIdx.x;
    if (i < NOUT / 4) {
        float4* o4 = (float4*)out;
        int r = i >> 4;   // 16 float4 per (token,d) row
        float s = 1.0f / (g_cnt[r] + 1e-5f);
        float4 vv = o4[i];
        vv.x *= s; vv.y *= s; vv.z *= s; vv.w *= s;
        o4[i] = vv;
    }
    if (i == 0 && out_size > NOUT) {
        out[NOUT] = (float)(g_aux / ((double)B * H * 2 * T * D) * 1e-4);
    }
}

extern "C" void kernel_launch(void* const* d_in, const int* in_sizes, int n_in,
                              void* d_out, int out_size) {
    const float* q         = (const float*)d_in[0];
    const float* k         = (const float*)d_in[1];
    const float* v         = (const float*)d_in[2];
    const float* means     = (const float*)d_in[3];
    const float* mem_key   = (const float*)d_in[4];
    const float* mem_value = (const float*)d_in[5];
    float* out = (float*)d_out;

    int tk_smem = (T + NBINS) * 4;                       // 49152
    int at_smem = (64 * 64 + 65 * 64 * 2 + 64 * 65 + 128) * 4;  // 66816
    cudaFuncSetAttribute(topk_kernel, cudaFuncAttributeMaxDynamicSharedMemorySize, tk_smem);
    cudaFuncSetAttribute(attn_kernel, cudaFuncAttributeMaxDynamicSharedMemorySize, at_smem);

    zero_kernel<<<(out_size + 255) / 256, 256>>>(out, out_size);
    mnorm_kernel<<<(H * NC + 255) / 256, 256>>>(means);
    dist_kernel<<<dim3(2 * T / 128, H, B), 128>>>(q, k, means);
    topk_kernel<<<B * H * 2 * NC, 256, tk_smem>>>();
    attn_kernel<<<B * H * NC, 256, at_smem>>>(q, k, v, mem_key, mem_value, out);
    finalize_kernel<<<(NOUT / 4 + 255) / 256, 256>>>(out, out_size);
}

// round 2
// speedup vs baseline: 2.1593x; 2.1593x over previous
#include <cuda_runtime.h>
#include <math.h>

#define B 4
#define H 8
#define T 8192
#define D 64
#define NC 128
#define W 64
#define NTOK (B*H*T)          /* 262144 */
#define NOUT (B*H*T*D)        /* 16777216 */
#define NBINS 4096
#define CANDCAP 512

typedef unsigned long long ull;

// packed fp32x2 FMA (Blackwell double-rate fp32; only reachable via PTX)
#define FMA2(acc, a, b) asm("fma.rn.f32x2 %0, %1, %2, %0;" : "+l"(acc) : "l"(a), "l"(b))

__device__ __forceinline__ ull pk2(float a, float b) {
    ull r;
    asm("mov.b64 %0, {%1, %2};" : "=l"(r) : "r"(__float_as_uint(a)), "r"(__float_as_uint(b)));
    return r;
}
__device__ __forceinline__ float2 upk2(ull p) {
    unsigned lo, hi;
    asm("mov.b64 {%0, %1}, %2;" : "=r"(lo), "=r"(hi) : "l"(p));
    return make_float2(__uint_as_float(lo), __uint_as_float(hi));
}

// -------- device scratch (no allocations allowed) --------
__device__ float  g_dists[(size_t)B*H*2*NC*T];   // [bh][s][c][t]
__device__ float  g_mnorm2[H*NC];
__device__ int    g_qidx[B*H*NC*W];
__device__ int    g_kidx[B*H*NC*W];
__device__ float  g_cnt[NTOK];
__device__ double g_aux;

// ---------------------------------------------------------
__global__ void zero_kernel(float* out, int out_size) {
    int i = blockIdx.x * blockDim.x + threadIdx.x;
    if (i < out_size) out[i] = 0.0f;
    if (i < NTOK) g_cnt[i] = 0.0f;
    if (i == 0) g_aux = 0.0;
}

__global__ void mnorm_kernel(const float* __restrict__ means) {
    int i = blockIdx.x * blockDim.x + threadIdx.x;
    if (i < H * NC) {
        const float* m = means + (size_t)i * D;
        float s = 0.f;
        #pragma unroll
        for (int d = 0; d < D; d++) { float x = m[d]; s += x * x; }
        g_mnorm2[i] = s;
    }
}

// ===================== dist: tiled 128tok x 128cl x 64 GEMM, f32x2 =====================
// grid (128 tiles, H, B), block 256. tiles 0..63 -> q, 64..127 -> k.
extern __shared__ float ds_dyn[];
__global__ __launch_bounds__(256, 2)
void dist_kernel(const float* __restrict__ q,
                 const float* __restrict__ k,
                 const float* __restrict__ means) {
    float* mT    = ds_dyn;                 // [64][128] transposed means
    float* xT    = mT + 64 * 128;          // [64][128] transposed normalized x
    float* s_xn2 = xT + 64 * 128;          // [128]
    float* amaxv = s_xn2 + 128;            // [128][16]
    int*   amaxi = (int*)(amaxv + 128*16); // [128][16]
    float* red   = (float*)(amaxi + 128*16); // [256]

    int h = blockIdx.y, b = blockIdx.z;
    int bh = b * H + h;
    int tile = blockIdx.x;
    int s = tile >> 6;
    int t0 = (tile & 63) * 128;
    int tid = threadIdx.x;

    // means transpose (coalesced-ish read, conflict-free smem writes)
    const float4* mh4 = (const float4*)(means + (size_t)h * NC * D);
    for (int i = tid; i < NC * 16; i += 256) {
        int c = i & 127, dq = i >> 7;
        float4 mv = mh4[c * 16 + dq];
        mT[(4*dq+0)*128 + c] = mv.x;
        mT[(4*dq+1)*128 + c] = mv.y;
        mT[(4*dq+2)*128 + c] = mv.z;
        mT[(4*dq+3)*128 + c] = mv.w;
    }

    // x tile: 128 tokens; first 128 threads each normalize one token and write transposed
    if (tid < 128) {
        const float* src = s ? k : q;
        const float4* xr = (const float4*)(src + ((size_t)bh * T + t0 + tid) * D);
        float4 xv[16]; float n2 = 0.f;
        #pragma unroll
        for (int i = 0; i < 16; i++) {
            float4 v = xr[i]; xv[i] = v;
            n2 += v.x*v.x + v.y*v.y + v.z*v.z + v.w*v.w;
        }
        float nrm = sqrtf(n2);
        float inv = 1.0f / fmaxf(nrm, 1e-12f);
        s_xn2[tid] = n2 * inv * inv;
        #pragma unroll
        for (int i = 0; i < 16; i++) {
            xT[(4*i+0)*128 + tid] = xv[i].x * inv;
            xT[(4*i+1)*128 + tid] = xv[i].y * inv;
            xT[(4*i+2)*128 + tid] = xv[i].z * inv;
            xT[(4*i+3)*128 + tid] = xv[i].w * inv;
        }
    }
    __syncthreads();

    int tx = tid & 15, ty = tid >> 4;
    int cb = ty * 8;                       // 8 clusters (4 pairs)
    ull acc[8][4];
    #pragma unroll
    for (int j = 0; j < 8; j++)
        #pragma unroll
        for (int p = 0; p < 4; p++) acc[j][p] = 0ull;

    #pragma unroll 4
    for (int d = 0; d < 64; d++) {
        const float* mrow = mT + d * 128 + cb;
        ull m0 = *(const ull*)(mrow + 0);
        ull m1 = *(const ull*)(mrow + 2);
        ull m2 = *(const ull*)(mrow + 4);
        ull m3 = *(const ull*)(mrow + 6);
        const float* xrow = xT + d * 128 + tx;
        #pragma unroll
        for (int j = 0; j < 8; j++) {
            float xv = xrow[16 * j];
            ull xx = pk2(xv, xv);
            FMA2(acc[j][0], xx, m0);
            FMA2(acc[j][1], xx, m1);
            FMA2(acc[j][2], xx, m2);
            FMA2(acc[j][3], xx, m3);
        }
    }

    // store + per-thread argmax (scan ascending c with strict > => lowest c on ties)
    size_t obase = (((size_t)bh * 2 + s) * NC) * T + t0;
    #pragma unroll
    for (int j = 0; j < 8; j++) {
        int tok = tx + 16 * j;
        float bv = -1e30f; int bc = 0;
        #pragma unroll
        for (int p = 0; p < 4; p++) {
            float2 vv = upk2(acc[j][p]);
            int c = cb + 2 * p;
            g_dists[obase + (size_t)c * T + tok]       = vv.x;
            g_dists[obase + (size_t)(c + 1) * T + tok] = vv.y;
            if (vv.x > bv) { bv = vv.x; bc = c; }
            if (vv.y > bv) { bv = vv.y; bc = c + 1; }
        }
        amaxv[tok * 16 + ty] = bv;
        amaxi[tok * 16 + ty] = bc;
    }
    __syncthreads();

    // reduce argmax per token (ascending ty keeps lowest c on ties), aux contribution
    if (tid < 128) {
        float bv = -1e30f; int bc = 0;
        #pragma unroll
        for (int t2 = 0; t2 < 16; t2++) {
            float v = amaxv[tid * 16 + t2];
            if (v > bv) { bv = v; bc = amaxi[tid * 16 + t2]; }
        }
        red[tid] = s_xn2[tid] - 2.f * bv + g_mnorm2[h * NC + bc];
    } else red[tid] = 0.f;
    __syncthreads();
    for (int o = 128; o > 0; o >>= 1) {
        if (tid < o) red[tid] += red[tid + o];
        __syncthreads();
    }
    if (tid == 0) atomicAdd(&g_aux, (double)red[0]);
}

// ===================== topk: exact top-64 per (bh,s,c), 512 threads =====================
extern __shared__ float tk_dyn[];   // sv[T] then hist[NBINS]
__global__ void topk_kernel() {
    float* sv = tk_dyn;
    int* hist = (int*)(tk_dyn + T);
    __shared__ int   csum[512];
    __shared__ int   s_bstar, s_nOut, s_nCand;
    __shared__ float candV[CANDCAP];
    __shared__ int   candI[CANDCAP];

    int bid = blockIdx.x;
    int c = bid % NC;
    int s = (bid / NC) & 1;
    int bh = bid / (2 * NC);
    int h = bh % H;
    int tid = threadIdx.x;

    const float* dp = g_dists + (((size_t)bh * 2 + s) * NC + c) * T;
    for (int i = tid; i < T; i += 512) sv[i] = dp[i];
    for (int i = tid; i < NBINS; i += 512) hist[i] = 0;
    if (tid == 0) { s_nOut = 0; s_nCand = 0; }
    __syncthreads();

    float mn = sqrtf(g_mnorm2[h * NC + c]);
    float lo = -mn;
    float scaleb = (float)NBINS / (2.0f * mn);

    for (int i = tid; i < T; i += 512) {
        int bin = (int)((sv[i] - lo) * scaleb);
        bin = min(max(bin, 0), NBINS - 1);
        atomicAdd(&hist[bin], 1);
    }
    __syncthreads();

    // per-thread chunk of 8 bins; inclusive suffix scan over 512 chunks
    int orig = 0;
    #pragma unroll
    for (int bb = 0; bb < 8; bb++) orig += hist[tid * 8 + bb];
    csum[tid] = orig; __syncthreads();
    for (int st = 1; st < 512; st <<= 1) {
        int add = (tid + st < 512) ? csum[tid + st] : 0;
        __syncthreads();
        csum[tid] += add;
        __syncthreads();
    }
    int E = csum[tid] - orig;   // strictly above this chunk
    if (E < W && E + orig >= W) {
        int cum = E;
        for (int bb = 7; bb >= 0; bb--) {
            int hc = hist[tid * 8 + bb];
            if (cum + hc >= W) { s_bstar = tid * 8 + bb; break; }
            cum += hc;
        }
    }
    __syncthreads();
    int bstar = s_bstar;

    int* outPtr = (s == 0 ? g_qidx : g_kidx) + ((size_t)bh * NC + c) * W;
    for (int i = tid; i < T; i += 512) {
        int bin = (int)((sv[i] - lo) * scaleb);
        bin = min(max(bin, 0), NBINS - 1);
        if (bin > bstar) {
            int p = atomicAdd(&s_nOut, 1);
            outPtr[p] = i;
        } else if (bin == bstar) {
            int p = atomicAdd(&s_nCand, 1);
            if (p < CANDCAP) { candV[p] = sv[i]; candI[p] = i; }
        }
    }
    __syncthreads();

    if (tid == 0) {
        int nOut = s_nOut;
        int need = W - nOut;
        int ncand = min(s_nCand, CANDCAP);
        for (int r = 0; r < need; r++) {
            float bv = -1e30f; int bi = 0x7fffffff; int bp = -1;
            for (int m = 0; m < ncand; m++) {
                if (candI[m] >= 0) {
                    float vv = candV[m];
                    if (vv > bv || (vv == bv && candI[m] < bi)) { bv = vv; bi = candI[m]; bp = m; }
                }
            }
            outPtr[nOut + r] = bi;
            candI[bp] = -1;
        }
    }
}

// ===================== attn: tiled QK / AV with f32x2, memory slot at j=64 =====================
#define QT_S 66   /* stride for transposed q/k tiles (8B-aligned rows, conflict-light) */
extern __shared__ float at_dyn[];
__global__ __launch_bounds__(256, 2)
void attn_kernel(const float* __restrict__ q,
                 const float* __restrict__ k,
                 const float* __restrict__ v,
                 const float* __restrict__ mem_key,
                 const float* __restrict__ mem_value,
                 float* __restrict__ out) {
    float* qT  = at_dyn;                // [64 d][66]  cols 0..63 = q rows
    float* kT  = qT + 64 * QT_S;        // [64 d][66]  cols 0..64 = k rows (64 = mem)
    float* vs  = kT + 64 * QT_S;        // [65 j][64 d]
    float* scT = vs + 65 * 64;          // [65 j][64 q]
    int* qi = (int*)(scT + 65 * 64);
    int* ki = qi + 64;

    int bid = blockIdx.x;
    int c = bid % NC;
    int bh = bid / NC;
    int h = bh % H;
    int tid = threadIdx.x;

    if (tid < 64)       qi[tid]      = g_qidx[((size_t)bh * NC + c) * W + tid];
    else if (tid < 128) ki[tid - 64] = g_kidx[((size_t)bh * NC + c) * W + tid - 64];
    __syncthreads();

    // gather Q -> qT transposed
    for (int idx = tid; idx < 64 * 64; idx += 256) {
        int r = idx >> 6, col = idx & 63;
        qT[col * QT_S + r] = q[((size_t)bh * T + qi[r]) * D + col];
    }
    // gather K -> kT transposed, V -> vs row-major; memory slot at j=64
    for (int idx = tid; idx < 64 * 64; idx += 256) {
        int r = idx >> 6, col = idx & 63;
        kT[col * QT_S + r] = k[((size_t)bh * T + ki[r]) * D + col];
        vs[r * 64 + col]   = v[((size_t)bh * T + ki[r]) * D + col];
    }
    for (int col = tid; col < 64; col += 256) {
        kT[col * QT_S + 64] = mem_key[((size_t)h * NC + c) * D + col];
        vs[64 * 64 + col]   = mem_value[((size_t)h * NC + c) * D + col];
    }
    __syncthreads();

    const float scale = 0.125f;   // d^-0.5
    int tx = tid & 15, ty = tid >> 4;

    // ---- QK: thread tile 4q x 4k over cols 0..63 ----
    {
        int qb = 4 * tx, kb = 4 * ty;
        ull acc[2][4];
        #pragma unroll
        for (int p = 0; p < 2; p++)
            #pragma unroll
            for (int i = 0; i < 4; i++) acc[p][i] = 0ull;
        #pragma unroll 4
        for (int d = 0; d < 64; d++) {
            const float* qrow = qT + d * QT_S + qb;
            ull q0 = *(const ull*)(qrow);
            ull q1 = *(const ull*)(qrow + 2);
            const float* krow = kT + d * QT_S + kb;
            #pragma unroll
            for (int i = 0; i < 4; i++) {
                ull kk = pk2(krow[i], krow[i]);
                FMA2(acc[0][i], q0, kk);
                FMA2(acc[1][i], q1, kk);
            }
        }
        #pragma unroll
        for (int p = 0; p < 2; p++)
            #pragma unroll
            for (int i = 0; i < 4; i++) {
                float2 vv = upk2(acc[p][i]);
                scT[(kb + i) * 64 + qb + 2*p]     = vv.x * scale;
                scT[(kb + i) * 64 + qb + 2*p + 1] = vv.y * scale;
            }
    }
    // ---- QK column 64 (memory key): one thread per q row ----
    if (tid < 64) {
        float a = 0.f;
        for (int d = 0; d < 64; d++) a += qT[d * QT_S + tid] * kT[d * QT_S + 64];
        scT[64 * 64 + tid] = a * scale;
    }
    __syncthreads();

    // ---- softmax per q row (thread per row; bank-parallel strided column walk) ----
    if (tid < 64) {
        float mx = -1e30f;
        for (int j = 0; j < 65; j++) mx = fmaxf(mx, scT[j * 64 + tid]);
        float sum = 0.f;
        for (int j = 0; j < 65; j++) {
            float e = __expf(scT[j * 64 + tid] - mx);
            scT[j * 64 + tid] = e;
            sum += e;
        }
        float rinv = 1.0f / sum;
        for (int j = 0; j < 65; j++) scT[j * 64 + tid] *= rinv;
    }
    __syncthreads();

    // ---- AV: thread tile 4q x 4d over 65 kv ----
    {
        int qb = 4 * tx, db = 4 * ty;
        ull o2[2][4];
        #pragma unroll
        for (int p = 0; p < 2; p++)
            #pragma unroll
            for (int i = 0; i < 4; i++) o2[p][i] = 0ull;
        #pragma unroll 4
        for (int j = 0; j < 65; j++) {
            const float* prow = scT + j * 64 + qb;
            ull p0 = *(const ull*)(prow);
            ull p1 = *(const ull*)(prow + 2);
            const float* vrow = vs + j * 64 + db;
            #pragma unroll
            for (int i = 0; i < 4; i++) {
                ull vv = pk2(vrow[i], vrow[i]);
                FMA2(o2[0][i], p0, vv);
                FMA2(o2[1][i], p1, vv);
            }
        }
        #pragma unroll
        for (int p = 0; p < 2; p++) {
            int r0 = qb + 2 * p;
            int tokA = qi[r0], tokB = qi[r0 + 1];
            float* opA = out + ((size_t)bh * T + tokA) * D + db;
            float* opB = out + ((size_t)bh * T + tokB) * D + db;
            #pragma unroll
            for (int i = 0; i < 4; i++) {
                float2 vv = upk2(o2[p][i]);
                atomicAdd(opA + i, vv.x);
                atomicAdd(opB + i, vv.y);
            }
        }
    }
    if (tid < 64) atomicAdd(&g_cnt[(size_t)bh * T + qi[tid]], 1.0f);
}

__global__ void finalize_kernel(float* out, int out_size) {
    int i = blockIdx.x * blockDim.x + threadIdx.x;
    if (i < NOUT / 4) {
        float4* o4 = (float4*)out;
        int r = i >> 4;
        float s = 1.0f / (g_cnt[r] + 1e-5f);
        float4 vv = o4[i];
        vv.x *= s; vv.y *= s; vv.z *= s; vv.w *= s;
        o4[i] = vv;
    }
    if (i == 0 && out_size > NOUT) {
        out[NOUT] = (float)(g_aux / ((double)B * H * 2 * T * D) * 1e-4);
    }
}

extern "C" void kernel_launch(void* const* d_in, const int* in_sizes, int n_in,
                              void* d_out, int out_size) {
    const float* q         = (const float*)d_in[0];
    const float* k         = (const float*)d_in[1];
    const float* v         = (const float*)d_in[2];
    const float* means     = (const float*)d_in[3];
    const float* mem_key   = (const float*)d_in[4];
    const float* mem_value = (const float*)d_in[5];
    float* out = (float*)d_out;

    int ds_smem = (64*128 + 64*128 + 128 + 128*16 + 128*16 + 256) * 4;  // 83456
    int tk_smem = (T + NBINS) * 4;                                      // 49152
    int at_smem = (64*QT_S*2 + 65*64*2 + 128) * 4;                      // 67584
    cudaFuncSetAttribute(dist_kernel, cudaFuncAttributeMaxDynamicSharedMemorySize, ds_smem);
    cudaFuncSetAttribute(topk_kernel, cudaFuncAttributeMaxDynamicSharedMemorySize, tk_smem);
    cudaFuncSetAttribute(attn_kernel, cudaFuncAttributeMaxDynamicSharedMemorySize, at_smem);

    zero_kernel<<<(out_size + 255) / 256, 256>>>(out, out_size);
    mnorm_kernel<<<(H * NC + 255) / 256, 256>>>(means);
    dist_kernel<<<dim3(128, H, B), 256, ds_smem>>>(q, k, means);
    topk_kernel<<<B * H * 2 * NC, 512, tk_smem>>>();
    attn_kernel<<<B * H * NC, 256, at_smem>>>(q, k, v, mem_key, mem_value, out);
    finalize_kernel<<<(NOUT / 4 + 255) / 256, 256>>>(out, out_size);
}

// round 3
// speedup vs baseline: 2.8428x; 1.3166x over previous
#include <cuda_runtime.h>
#include <math.h>

#define B 4
#define H 8
#define T 8192
#define D 64
#define NC 128
#define W 64
#define NTOK (B*H*T)          /* 262144 */
#define NOUT (B*H*T*D)        /* 16777216 */
#define NBINS 4096
#define CANDCAP 512

typedef unsigned long long ull;

// packed fp32x2 FMA (Blackwell double-rate fp32; only reachable via PTX)
#define FMA2(acc, a, b) asm("fma.rn.f32x2 %0, %1, %2, %0;" : "+l"(acc) : "l"(a), "l"(b))
// vectorized float reduction to global (sm_90+)
#define RED4(p, a, b, c, d) asm volatile("red.global.add.v4.f32 [%0], {%1,%2,%3,%4};" :: "l"(p), "f"(a), "f"(b), "f"(c), "f"(d) : "memory")

__device__ __forceinline__ ull pk2(float a, float b) {
    ull r;
    asm("mov.b64 %0, {%1, %2};" : "=l"(r) : "r"(__float_as_uint(a)), "r"(__float_as_uint(b)));
    return r;
}
__device__ __forceinline__ float2 upk2(ull p) {
    unsigned lo, hi;
    asm("mov.b64 {%0, %1}, %2;" : "=r"(lo), "=r"(hi) : "l"(p));
    return make_float2(__uint_as_float(lo), __uint_as_float(hi));
}

// -------- device scratch (no allocations allowed) --------
__device__ float  g_dists[(size_t)B*H*2*NC*T];   // [bh][s][c][t]
__device__ float  g_mnorm2[H*NC];
__device__ int    g_qidx[B*H*NC*W];
__device__ int    g_kidx[B*H*NC*W];
__device__ float  g_cnt[NTOK];
__device__ double g_aux;

// ---------------------------------------------------------
__global__ void zero_small_kernel() {
    int i = blockIdx.x * blockDim.x + threadIdx.x;
    if (i < NTOK) g_cnt[i] = 0.0f;
    if (i == 0) g_aux = 0.0;
}

__global__ void mnorm_kernel(const float* __restrict__ means) {
    int i = blockIdx.x * blockDim.x + threadIdx.x;
    if (i < H * NC) {
        const float* m = means + (size_t)i * D;
        float s = 0.f;
        #pragma unroll
        for (int d = 0; d < D; d++) { float x = m[d]; s += x * x; }
        g_mnorm2[i] = s;
    }
}

// ===================== dist: tiled 128tok x 128cl x 64 GEMM, f32x2 =====================
extern __shared__ float ds_dyn[];
__global__ __launch_bounds__(256, 2)
void dist_kernel(const float* __restrict__ q,
                 const float* __restrict__ k,
                 const float* __restrict__ means) {
    float* mT    = ds_dyn;                 // [64][128]
    float* xT    = mT + 64 * 128;          // [64][128]
    float* s_xn2 = xT + 64 * 128;          // [128]
    float* amaxv = s_xn2 + 128;            // [128][16]
    int*   amaxi = (int*)(amaxv + 128*16); // [128][16]
    float* red   = (float*)(amaxi + 128*16); // [256]

    int h = blockIdx.y, b = blockIdx.z;
    int bh = b * H + h;
    int tile = blockIdx.x;
    int s = tile >> 6;
    int t0 = (tile & 63) * 128;
    int tid = threadIdx.x;

    const float4* mh4 = (const float4*)(means + (size_t)h * NC * D);
    for (int i = tid; i < NC * 16; i += 256) {
        int c = i & 127, dq = i >> 7;
        float4 mv = mh4[c * 16 + dq];
        mT[(4*dq+0)*128 + c] = mv.x;
        mT[(4*dq+1)*128 + c] = mv.y;
        mT[(4*dq+2)*128 + c] = mv.z;
        mT[(4*dq+3)*128 + c] = mv.w;
    }

    if (tid < 128) {
        const float* src = s ? k : q;
        const float4* xr = (const float4*)(src + ((size_t)bh * T + t0 + tid) * D);
        float4 xv[16]; float n2 = 0.f;
        #pragma unroll
        for (int i = 0; i < 16; i++) {
            float4 v = xr[i]; xv[i] = v;
            n2 += v.x*v.x + v.y*v.y + v.z*v.z + v.w*v.w;
        }
        float nrm = sqrtf(n2);
        float inv = 1.0f / fmaxf(nrm, 1e-12f);
        s_xn2[tid] = n2 * inv * inv;
        #pragma unroll
        for (int i = 0; i < 16; i++) {
            xT[(4*i+0)*128 + tid] = xv[i].x * inv;
            xT[(4*i+1)*128 + tid] = xv[i].y * inv;
            xT[(4*i+2)*128 + tid] = xv[i].z * inv;
            xT[(4*i+3)*128 + tid] = xv[i].w * inv;
        }
    }
    __syncthreads();

    int tx = tid & 15, ty = tid >> 4;
    int cb = ty * 8;
    ull acc[8][4];
    #pragma unroll
    for (int j = 0; j < 8; j++)
        #pragma unroll
        for (int p = 0; p < 4; p++) acc[j][p] = 0ull;

    #pragma unroll 4
    for (int d = 0; d < 64; d++) {
        const float* mrow = mT + d * 128 + cb;
        ull m0 = *(const ull*)(mrow + 0);
        ull m1 = *(const ull*)(mrow + 2);
        ull m2 = *(const ull*)(mrow + 4);
        ull m3 = *(const ull*)(mrow + 6);
        const float* xrow = xT + d * 128 + tx;
        #pragma unroll
        for (int j = 0; j < 8; j++) {
            float xv = xrow[16 * j];
            ull xx = pk2(xv, xv);
            FMA2(acc[j][0], xx, m0);
            FMA2(acc[j][1], xx, m1);
            FMA2(acc[j][2], xx, m2);
            FMA2(acc[j][3], xx, m3);
        }
    }

    size_t obase = (((size_t)bh * 2 + s) * NC) * T + t0;
    #pragma unroll
    for (int j = 0; j < 8; j++) {
        int tok = tx + 16 * j;
        float bv = -1e30f; int bc = 0;
        #pragma unroll
        for (int p = 0; p < 4; p++) {
            float2 vv = upk2(acc[j][p]);
            int c = cb + 2 * p;
            g_dists[obase + (size_t)c * T + tok]       = vv.x;
            g_dists[obase + (size_t)(c + 1) * T + tok] = vv.y;
            if (vv.x > bv) { bv = vv.x; bc = c; }
            if (vv.y > bv) { bv = vv.y; bc = c + 1; }
        }
        amaxv[tok * 16 + ty] = bv;
        amaxi[tok * 16 + ty] = bc;
    }
    __syncthreads();

    if (tid < 128) {
        float bv = -1e30f; int bc = 0;
        #pragma unroll
        for (int t2 = 0; t2 < 16; t2++) {
            float v = amaxv[tid * 16 + t2];
            if (v > bv) { bv = v; bc = amaxi[tid * 16 + t2]; }
        }
        red[tid] = s_xn2[tid] - 2.f * bv + g_mnorm2[h * NC + bc];
    } else red[tid] = 0.f;
    __syncthreads();
    for (int o = 128; o > 0; o >>= 1) {
        if (tid < o) red[tid] += red[tid + o];
        __syncthreads();
    }
    if (tid == 0) atomicAdd(&g_aux, (double)red[0]);
}

// ===================== topk: register-resident exact top-64 =====================
__global__ __launch_bounds__(512, 2) void topk_kernel() {
    __shared__ int   hist[NBINS];
    __shared__ int   csum[512];
    __shared__ int   s_bstar, s_nOut, s_nCand;
    __shared__ float candV[CANDCAP];
    __shared__ int   candI[CANDCAP];

    int bid = blockIdx.x;
    int c = bid % NC;
    int s = (bid / NC) & 1;
    int bh = bid / (2 * NC);
    int h = bh % H;
    int tid = threadIdx.x;

    const float4* dp4 = (const float4*)(g_dists + (((size_t)bh * 2 + s) * NC + c) * T);
    float4 v4[4];
    #pragma unroll
    for (int j = 0; j < 4; j++) v4[j] = dp4[tid + 512 * j];

    for (int i = tid; i < NBINS; i += 512) hist[i] = 0;
    if (tid == 0) { s_nOut = 0; s_nCand = 0; }
    __syncthreads();

    float mn = sqrtf(g_mnorm2[h * NC + c]);
    float lo = -mn;
    float scaleb = (float)NBINS / (2.0f * mn);

    float vals[16];
    #pragma unroll
    for (int j = 0; j < 4; j++) {
        vals[4*j+0] = v4[j].x; vals[4*j+1] = v4[j].y;
        vals[4*j+2] = v4[j].z; vals[4*j+3] = v4[j].w;
    }
    #pragma unroll
    for (int i = 0; i < 16; i++) {
        int bin = (int)((vals[i] - lo) * scaleb);
        bin = min(max(bin, 0), NBINS - 1);
        atomicAdd(&hist[bin], 1);
    }
    __syncthreads();

    int orig = 0;
    #pragma unroll
    for (int bb = 0; bb < 8; bb++) orig += hist[tid * 8 + bb];
    csum[tid] = orig; __syncthreads();
    for (int st = 1; st < 512; st <<= 1) {
        int add = (tid + st < 512) ? csum[tid + st] : 0;
        __syncthreads();
        csum[tid] += add;
        __syncthreads();
    }
    int E = csum[tid] - orig;
    if (E < W && E + orig >= W) {
        int cum = E;
        for (int bb = 7; bb >= 0; bb--) {
            int hc = hist[tid * 8 + bb];
            if (cum + hc >= W) { s_bstar = tid * 8 + bb; break; }
            cum += hc;
        }
    }
    __syncthreads();
    int bstar = s_bstar;

    int* outPtr = (s == 0 ? g_qidx : g_kidx) + ((size_t)bh * NC + c) * W;
    #pragma unroll
    for (int i = 0; i < 16; i++) {
        int bin = (int)((vals[i] - lo) * scaleb);
        bin = min(max(bin, 0), NBINS - 1);
        if (bin >= bstar) {
            int gi = 4 * (tid + 512 * (i >> 2)) + (i & 3);
            if (bin > bstar) {
                int p = atomicAdd(&s_nOut, 1);
                outPtr[p] = gi;
            } else {
                int p = atomicAdd(&s_nCand, 1);
                if (p < CANDCAP) { candV[p] = vals[i]; candI[p] = gi; }
            }
        }
    }
    __syncthreads();

    if (tid == 0) {
        int nOut = s_nOut;
        int need = W - nOut;
        int ncand = min(s_nCand, CANDCAP);
        for (int r = 0; r < need; r++) {
            float bv = -1e30f; int bi = 0x7fffffff; int bp = -1;
            for (int m = 0; m < ncand; m++) {
                if (candI[m] >= 0) {
                    float vv = candV[m];
                    if (vv > bv || (vv == bv && candI[m] < bi)) { bv = vv; bi = candI[m]; bp = m; }
                }
            }
            outPtr[nOut + r] = bi;
            candI[bp] = -1;
        }
    }
}

// ===================== attn =====================
#define QT_S 66
#define SC_S 72   /* 72 mod 32 == 8: row + 8*part hits distinct banks in softmax */
extern __shared__ float at_dyn[];
__global__ __launch_bounds__(256, 2)
void attn_kernel(const float* __restrict__ q,
                 const float* __restrict__ k,
                 const float* __restrict__ v,
                 const float* __restrict__ mem_key,
                 const float* __restrict__ mem_value,
                 float* __restrict__ out) {
    float* qT  = at_dyn;                // [64 d][66]  cols 0..63 = q rows (pre-scaled)
    float* kT  = qT + 64 * QT_S;        // [64 d][66]  cols 0..64 (64 = mem)
    float* vs  = kT + 64 * QT_S;        // [65 j][64 d]
    float* scT = vs + 65 * 64;          // [65 j][72]
    int* qi = (int*)(scT + 65 * SC_S);
    int* ki = qi + 64;

    int bid = blockIdx.x;
    int c = bid % NC;
    int bh = bid / NC;
    int h = bh % H;
    int tid = threadIdx.x;

    if (tid < 64)       qi[tid]      = g_qidx[((size_t)bh * NC + c) * W + tid];
    else if (tid < 128) ki[tid - 64] = g_kidx[((size_t)bh * NC + c) * W + tid - 64];
    __syncthreads();

    const float scale = 0.125f;   // d^-0.5 folded into q
    // gather (float4 loads)
    #pragma unroll
    for (int it = 0; it < 4; it++) {
        int idx = tid + 256 * it;           // 1024 slots = 64 rows x 16 float4
        int r = idx >> 4, c4 = idx & 15;
        float4 qv = ((const float4*)(q + ((size_t)bh * T + qi[r]) * D))[c4];
        qT[(4*c4+0)*QT_S + r] = qv.x * scale;
        qT[(4*c4+1)*QT_S + r] = qv.y * scale;
        qT[(4*c4+2)*QT_S + r] = qv.z * scale;
        qT[(4*c4+3)*QT_S + r] = qv.w * scale;
        float4 kv = ((const float4*)(k + ((size_t)bh * T + ki[r]) * D))[c4];
        kT[(4*c4+0)*QT_S + r] = kv.x;
        kT[(4*c4+1)*QT_S + r] = kv.y;
        kT[(4*c4+2)*QT_S + r] = kv.z;
        kT[(4*c4+3)*QT_S + r] = kv.w;
        ((float4*)(vs + r * 64))[c4] = ((const float4*)(v + ((size_t)bh * T + ki[r]) * D))[c4];
    }
    if (tid < 16) {
        float4 mk = ((const float4*)(mem_key + ((size_t)h * NC + c) * D))[tid];
        kT[(4*tid+0)*QT_S + 64] = mk.x;
        kT[(4*tid+1)*QT_S + 64] = mk.y;
        kT[(4*tid+2)*QT_S + 64] = mk.z;
        kT[(4*tid+3)*QT_S + 64] = mk.w;
        ((float4*)(vs + 64 * 64))[tid] = ((const float4*)(mem_value + ((size_t)h * NC + c) * D))[tid];
    }
    __syncthreads();

    int tx = tid & 15, ty = tid >> 4;

    // ---- QK: 4q x 4k tile (q pre-scaled) ----
    {
        int qb = 4 * tx, kb = 4 * ty;
        ull acc[2][4];
        #pragma unroll
        for (int p = 0; p < 2; p++)
            #pragma unroll
            for (int i = 0; i < 4; i++) acc[p][i] = 0ull;
        #pragma unroll 4
        for (int d = 0; d < 64; d++) {
            const float* qrow = qT + d * QT_S + qb;
            ull q0 = *(const ull*)(qrow);
            ull q1 = *(const ull*)(qrow + 2);
            const float* krow = kT + d * QT_S + kb;
            #pragma unroll
            for (int i = 0; i < 4; i++) {
                ull kk = pk2(krow[i], krow[i]);
                FMA2(acc[0][i], q0, kk);
                FMA2(acc[1][i], q1, kk);
            }
        }
        #pragma unroll
        for (int i = 0; i < 4; i++) {
            *(ull*)(scT + (kb + i) * SC_S + qb)     = acc[0][i];
            *(ull*)(scT + (kb + i) * SC_S + qb + 2) = acc[1][i];
        }
    }
    // ---- QK column 64 (memory key) ----
    if (tid < 64) {
        float a = 0.f;
        #pragma unroll 8
        for (int d = 0; d < 64; d++) a += qT[d * QT_S + tid] * kT[d * QT_S + 64];
        scT[64 * SC_S + tid] = a;
    }
    __syncthreads();

    // ---- softmax: 4 threads per q row ----
    {
        int row = tid >> 2, part = tid & 3;
        float mx = -1e30f;
        for (int j = part; j < 65; j += 4) mx = fmaxf(mx, scT[j * SC_S + row]);
        mx = fmaxf(mx, __shfl_xor_sync(0xffffffffu, mx, 1));
        mx = fmaxf(mx, __shfl_xor_sync(0xffffffffu, mx, 2));
        float sum = 0.f;
        for (int j = part; j < 65; j += 4) {
            float e = __expf(scT[j * SC_S + row] - mx);
            scT[j * SC_S + row] = e;
            sum += e;
        }
        sum += __shfl_xor_sync(0xffffffffu, sum, 1);
        sum += __shfl_xor_sync(0xffffffffu, sum, 2);
        float rinv = 1.0f / sum;
        for (int j = part; j < 65; j += 4) scT[j * SC_S + row] *= rinv;
    }
    __syncthreads();

    // ---- AV: 4q x 4d tile over 65 kv ----
    {
        int qb = 4 * tx, db = 4 * ty;
        ull o2[2][4];
        #pragma unroll
        for (int p = 0; p < 2; p++)
            #pragma unroll
            for (int i = 0; i < 4; i++) o2[p][i] = 0ull;
        #pragma unroll 4
        for (int j = 0; j < 65; j++) {
            const float* prow = scT + j * SC_S + qb;
            ull p0 = *(const ull*)(prow);
            ull p1 = *(const ull*)(prow + 2);
            const float* vrow = vs + j * 64 + db;
            #pragma unroll
            for (int i = 0; i < 4; i++) {
                ull vv = pk2(vrow[i], vrow[i]);
                FMA2(o2[0][i], p0, vv);
                FMA2(o2[1][i], p1, vv);
            }
        }
        #pragma unroll
        for (int p = 0; p < 2; p++) {
            int r0 = qb + 2 * p;
            float* opA = out + ((size_t)bh * T + qi[r0])     * D + db;
            float* opB = out + ((size_t)bh * T + qi[r0 + 1]) * D + db;
            float2 f0 = upk2(o2[p][0]), f1 = upk2(o2[p][1]);
            float2 f2 = upk2(o2[p][2]), f3 = upk2(o2[p][3]);
            RED4(opA, f0.x, f1.x, f2.x, f3.x);
            RED4(opB, f0.y, f1.y, f2.y, f3.y);
        }
    }
    if (tid < 64) atomicAdd(&g_cnt[(size_t)bh * T + qi[tid]], 1.0f);
}

__global__ void finalize_kernel(float* out, int out_size) {
    int i = blockIdx.x * blockDim.x + threadIdx.x;
    if (i < NOUT / 4) {
        float4* o4 = (float4*)out;
        int r = i >> 4;
        float s = 1.0f / (g_cnt[r] + 1e-5f);
        float4 vv = o4[i];
        vv.x *= s; vv.y *= s; vv.z *= s; vv.w *= s;
        o4[i] = vv;
    }
    if (i == 0 && out_size > NOUT) {
        out[NOUT] = (float)(g_aux / ((double)B * H * 2 * T * D) * 1e-4);
    }
}

extern "C" void kernel_launch(void* const* d_in, const int* in_sizes, int n_in,
                              void* d_out, int out_size) {
    const float* q         = (const float*)d_in[0];
    const float* k         = (const float*)d_in[1];
    const float* v         = (const float*)d_in[2];
    const float* means     = (const float*)d_in[3];
    const float* mem_key   = (const float*)d_in[4];
    const float* mem_value = (const float*)d_in[5];
    float* out = (float*)d_out;

    int ds_smem = (64*128 + 64*128 + 128 + 128*16 + 128*16 + 256) * 4;   // 83456
    int at_smem = (64*QT_S*2 + 65*64 + 65*SC_S + 128) * 4;               // 69664
    cudaFuncSetAttribute(dist_kernel, cudaFuncAttributeMaxDynamicSharedMemorySize, ds_smem);
    cudaFuncSetAttribute(attn_kernel, cudaFuncAttributeMaxDynamicSharedMemorySize, at_smem);

    cudaMemsetAsync(out, 0, (size_t)out_size * sizeof(float), 0);
    zero_small_kernel<<<NTOK / 256, 256>>>();
    mnorm_kernel<<<(H * NC + 255) / 256, 256>>>(means);
    dist_kernel<<<dim3(128, H, B), 256, ds_smem>>>(q, k, means);
    topk_kernel<<<B * H * 2 * NC, 512>>>();
    attn_kernel<<<B * H * NC, 256, at_smem>>>(q, k, v, mem_key, mem_value, out);
    finalize_kernel<<<(NOUT / 4 + 255) / 256, 256>>>(out, out_size);
}